// round 6
// baseline (speedup 1.0000x reference)
#include <cuda_runtime.h>
#include <cuda_bf16.h>
#include <cstdint>

#define N_COLS   32
#define CAT_DIM  2000
#define TOTAL    64000
#define HIDDEN   128
#define MAX_B    2048

// -------- device scratch (no allocations allowed) --------
__device__ float          g_WT[(size_t)TOTAL * HIDDEN];     // W_enc^T for coalesced gathers
__device__ __nv_bfloat16  g_Wd_hi[(size_t)TOTAL * HIDDEN];  // W_dec split bf16 high
__device__ __nv_bfloat16  g_Wd_lo[(size_t)TOTAL * HIDDEN];  // W_dec split bf16 low
__device__ __nv_bfloat16  g_y_hi[(size_t)MAX_B * HIDDEN];   // sigmoid(y) split
__device__ __nv_bfloat16  g_y_lo[(size_t)MAX_B * HIDDEN];

// ---------------------------------------------------------------------------
// 1) Fused prep: blocks [0,8000) transpose W_enc -> g_WT;
//    blocks [8000,16000) split W_dec fp32 -> bf16 (hi,lo).
//    Both are bandwidth-bound; fusing overlaps their DRAM traffic.
// ---------------------------------------------------------------------------
__global__ void prep_kernel(const float* __restrict__ W,
                            const float4* __restrict__ Wd) {
    if (blockIdx.x < 8000) {
        __shared__ float tile[32][33];
        int bx = blockIdx.x % 2000, by = blockIdx.x / 2000;
        int tx = threadIdx.x & 31, ty = threadIdx.x >> 5;   // 32 x 8
        int v = bx * 32 + tx;
        int h = by * 32 + ty;
        #pragma unroll
        for (int j = 0; j < 32; j += 8)
            tile[ty + j][tx] = W[(size_t)(h + j) * TOTAL + v];
        __syncthreads();
        int h2 = by * 32 + tx;
        int v2 = bx * 32 + ty;
        #pragma unroll
        for (int j = 0; j < 32; j += 8)
            g_WT[(size_t)(v2 + j) * HIDDEN + h2] = tile[tx][ty + j];
    } else {
        size_t i = (size_t)(blockIdx.x - 8000) * blockDim.x + threadIdx.x;
        float4 w = Wd[i];
        __nv_bfloat16 h0 = __float2bfloat16(w.x), h1 = __float2bfloat16(w.y);
        __nv_bfloat16 h2 = __float2bfloat16(w.z), h3 = __float2bfloat16(w.w);
        __nv_bfloat16 l0 = __float2bfloat16(w.x - __bfloat162float(h0));
        __nv_bfloat16 l1 = __float2bfloat16(w.y - __bfloat162float(h1));
        __nv_bfloat16 l2 = __float2bfloat16(w.z - __bfloat162float(h2));
        __nv_bfloat16 l3 = __float2bfloat16(w.w - __bfloat162float(h3));
        __nv_bfloat162* hi2 = (__nv_bfloat162*)g_Wd_hi;
        __nv_bfloat162* lo2 = (__nv_bfloat162*)g_Wd_lo;
        hi2[i * 2 + 0] = __nv_bfloat162(h0, h1);
        hi2[i * 2 + 1] = __nv_bfloat162(h2, h3);
        lo2[i * 2 + 0] = __nv_bfloat162(l0, l1);
        lo2[i * 2 + 1] = __nv_bfloat162(l2, l3);
    }
}

// ---------------------------------------------------------------------------
// 2) Encode: gather-sum + sigmoid; emit y (fp32 out) and split bf16 copies.
// ---------------------------------------------------------------------------
__global__ void encode_kernel(const int* __restrict__ x_cat,
                              const float* __restrict__ b_enc,
                              float* __restrict__ y_out) {
    int b = blockIdx.x;
    int h = threadIdx.x;
    __shared__ int gidx[N_COLS];
    if (h < N_COLS) gidx[h] = x_cat[b * N_COLS + h] + h * CAT_DIM;
    __syncthreads();
    float acc = b_enc[h];
    #pragma unroll
    for (int i = 0; i < N_COLS; i++)
        acc += g_WT[(size_t)gidx[i] * HIDDEN + h];
    float s = 1.0f / (1.0f + expf(-acc));
    if (y_out) y_out[(size_t)b * HIDDEN + h] = s;
    __nv_bfloat16 hi = __float2bfloat16(s);
    g_y_hi[(size_t)b * HIDDEN + h] = hi;
    g_y_lo[(size_t)b * HIDDEN + h] = __float2bfloat16(s - __bfloat162float(hi));
}

// ---------------------------------------------------------------------------
// 3) Decode GEMM via mma.sync m16n8k16 bf16 (3 accumulating passes).
//    CTA tile 128m x 128n, K=128 resident. 512 threads = 16 warps (4M x 4N),
//    warp tile 32x32 -> 4 warps/SMSP to hide HMMA/LDSM latency.
// ---------------------------------------------------------------------------
#define GM 128
#define GN 128
#define NTHREADS 512

#define OFF_BIAS   0
#define OFF_B_HI   1024
#define OFF_B_LO   (OFF_B_HI + 32768)
#define OFF_A0_HI  (OFF_B_LO + 32768)
#define OFF_A0_LO  (OFF_A0_HI + 32768)
#define OFF_A1_HI  (OFF_A0_LO + 32768)
#define OFF_A1_LO  (OFF_A1_HI + 32768)
#define SMEM_END   (OFF_A1_LO + 32768)
#define SMEM_NEED  (SMEM_END + 1024)

__device__ __forceinline__ uint32_t smem_u32(const void* p) {
    return (uint32_t)__cvta_generic_to_shared(p);
}
// Blocked-atom SW128 byte offset within a [128 rows x 128 k bf16] tile.
__device__ __forceinline__ uint32_t tile_off(int r, int i /*16B chunk 0..15*/) {
    uint32_t off = (uint32_t)(((r >> 3) + ((i >> 3) << 4)) << 10)
                 + (uint32_t)((r & 7) << 7) + (uint32_t)((i & 7) << 4);
    return off ^ ((off >> 3) & 0x70);
}
__device__ __forceinline__ void cp16(uint32_t dst, const void* src) {
    asm volatile("cp.async.cg.shared.global [%0], [%1], 16;"
                 :: "r"(dst), "l"(src) : "memory");
}
__device__ __forceinline__ void ldsm_x4(uint32_t* f, uint32_t addr) {
    asm volatile("ldmatrix.sync.aligned.m8n8.x4.shared.b16 {%0,%1,%2,%3}, [%4];"
                 : "=r"(f[0]), "=r"(f[1]), "=r"(f[2]), "=r"(f[3]) : "r"(addr));
}
__device__ __forceinline__ void mma_bf16(float* c, const uint32_t* a, const uint32_t* b) {
    asm volatile(
        "mma.sync.aligned.m16n8k16.row.col.f32.bf16.bf16.f32 "
        "{%0,%1,%2,%3}, {%4,%5,%6,%7}, {%8,%9}, {%0,%1,%2,%3};"
        : "+f"(c[0]), "+f"(c[1]), "+f"(c[2]), "+f"(c[3])
        : "r"(a[0]), "r"(a[1]), "r"(a[2]), "r"(a[3]), "r"(b[0]), "r"(b[1]));
}

__global__ __launch_bounds__(NTHREADS, 1)
void decode_gemm_mma(const float* __restrict__ bias, float* __restrict__ C,
                     int mBlocks) {
    extern __shared__ char smem_raw[];
    uint32_t raw = smem_u32(smem_raw);
    uint32_t base = (raw + 1023u) & ~1023u;
    char* sm = smem_raw + (base - raw);

    const int tid = threadIdx.x;
    const int wid = tid >> 5, lane = tid & 31;
    const int warpM = wid >> 2;          // 0..3
    const int warpN = wid & 3;           // 0..3
    const int v0 = blockIdx.x * GN;
    const int mPer = mBlocks / gridDim.y;
    const int mBeg = blockIdx.y * mPer;

    // bias stage
    if (tid < GN) *(float*)(sm + OFF_BIAS + tid * 4) = bias[v0 + tid];

    // B tile (hi+lo), swizzled (once per CTA). 2048 uint4 per tile.
    #pragma unroll
    for (int it = 0; it < 4; it++) {
        int idx = it * NTHREADS + tid;
        int r = idx >> 4, i = idx & 15;
        uint32_t so = tile_off(r, i);
        *(uint4*)(sm + OFF_B_HI + so) = ((const uint4*)(g_Wd_hi + (size_t)(v0 + r) * HIDDEN))[i];
        *(uint4*)(sm + OFF_B_LO + so) = ((const uint4*)(g_Wd_lo + (size_t)(v0 + r) * HIDDEN))[i];
    }

    // prefetch A tile 0 into buffer 0 (cp.async)
    {
        const int m0 = mBeg * GM;
        #pragma unroll
        for (int it = 0; it < 4; it++) {
            int idx = it * NTHREADS + tid;
            int r = idx >> 4, i = idx & 15;
            uint32_t so = tile_off(r, i);
            cp16(base + OFF_A0_HI + so, (const char*)(g_y_hi + (size_t)(m0 + r) * HIDDEN) + i * 16);
            cp16(base + OFF_A0_LO + so, (const char*)(g_y_lo + (size_t)(m0 + r) * HIDDEN) + i * 16);
        }
        asm volatile("cp.async.commit_group;" ::: "memory");
    }

    // per-thread ldmatrix base addresses
    const int aRow = warpM * 32 + (lane & 15);                      // + mt*16
    const int aChk = (lane >> 4);                                   // + ks*2
    const int bRow = warpN * 32 + ((lane >> 4) << 3) + (lane & 7);  // + bt*16
    const int bChk = (lane >> 3) & 1;                               // + ks*2

    const uint32_t AOFF[2][2] = {{base + OFF_A0_HI, base + OFF_A0_LO},
                                 {base + OFF_A1_HI, base + OFF_A1_LO}};

    for (int mi = 0; mi < mPer; mi++) {
        const int m0 = (mBeg + mi) * GM;
        const int buf = mi & 1;

        asm volatile("cp.async.wait_group 0;" ::: "memory");
        __syncthreads();

        // prefetch next A tile into the other buffer
        if (mi + 1 < mPer) {
            const int m1 = (mBeg + mi + 1) * GM;
            const uint32_t hiDst = AOFF[buf ^ 1][0], loDst = AOFF[buf ^ 1][1];
            #pragma unroll
            for (int it = 0; it < 4; it++) {
                int idx = it * NTHREADS + tid;
                int r = idx >> 4, i = idx & 15;
                uint32_t so = tile_off(r, i);
                cp16(hiDst + so, (const char*)(g_y_hi + (size_t)(m1 + r) * HIDDEN) + i * 16);
                cp16(loDst + so, (const char*)(g_y_lo + (size_t)(m1 + r) * HIDDEN) + i * 16);
            }
            asm volatile("cp.async.commit_group;" ::: "memory");
        }

        float acc[2][4][4];
        #pragma unroll
        for (int mt = 0; mt < 2; mt++)
            #pragma unroll
            for (int nt = 0; nt < 4; nt++)
                #pragma unroll
                for (int q = 0; q < 4; q++)
                    acc[mt][nt][q] = 0.0f;

        const uint32_t aHi = AOFF[buf][0], aLo = AOFF[buf][1];

        #pragma unroll
        for (int ks = 0; ks < 8; ks++) {
            uint32_t ah[2][4], al[2][4];
            #pragma unroll
            for (int mt = 0; mt < 2; mt++) {
                uint32_t so = tile_off(aRow + mt * 16, ks * 2 + aChk);
                ldsm_x4(ah[mt], aHi + so);
                ldsm_x4(al[mt], aLo + so);
            }
            uint32_t bh[4][2], bl[4][2];
            #pragma unroll
            for (int bt = 0; bt < 2; bt++) {
                uint32_t so = tile_off(bRow + bt * 16, ks * 2 + bChk);
                uint32_t fh[4], fl[4];
                ldsm_x4(fh, base + OFF_B_HI + so);
                ldsm_x4(fl, base + OFF_B_LO + so);
                bh[bt * 2 + 0][0] = fh[0]; bh[bt * 2 + 0][1] = fh[1];
                bh[bt * 2 + 1][0] = fh[2]; bh[bt * 2 + 1][1] = fh[3];
                bl[bt * 2 + 0][0] = fl[0]; bl[bt * 2 + 0][1] = fl[1];
                bl[bt * 2 + 1][0] = fl[2]; bl[bt * 2 + 1][1] = fl[3];
            }
            #pragma unroll
            for (int mt = 0; mt < 2; mt++)
                #pragma unroll
                for (int nt = 0; nt < 4; nt++) {
                    mma_bf16(acc[mt][nt], ah[mt], bh[nt]);
                    mma_bf16(acc[mt][nt], al[mt], bh[nt]);
                    mma_bf16(acc[mt][nt], ah[mt], bl[nt]);
                }
        }

        // epilogue: bias + float2 stores
        const int cCol = warpN * 32 + 2 * (lane & 3);
        const int cRow = warpM * 32 + (lane >> 2);
        #pragma unroll
        for (int mt = 0; mt < 2; mt++) {
            #pragma unroll
            for (int nt = 0; nt < 4; nt++) {
                int col = cCol + nt * 8;
                float bx = *(float*)(sm + OFF_BIAS + col * 4);
                float by = *(float*)(sm + OFF_BIAS + (col + 1) * 4);
                size_t r0 = (size_t)(m0 + cRow + mt * 16) * TOTAL + v0 + col;
                size_t r1 = r0 + 8 * TOTAL;
                float2 o0 = make_float2(acc[mt][nt][0] + bx, acc[mt][nt][1] + by);
                float2 o1 = make_float2(acc[mt][nt][2] + bx, acc[mt][nt][3] + by);
                *(float2*)&C[r0] = o0;
                *(float2*)&C[r1] = o1;
            }
        }
        __syncthreads();   // protect smem A buffer reuse ordering
    }
}

// ---------------------------------------------------------------------------
// Launch
// ---------------------------------------------------------------------------
extern "C" void kernel_launch(void* const* d_in, const int* in_sizes, int n_in,
                              void* d_out, int out_size) {
    const int*   x_cat = (const int*)d_in[0];
    const float* W_enc = (const float*)d_in[1];
    const float* b_enc = (const float*)d_in[2];
    const float* W_dec = (const float*)d_in[3];
    const float* b_dec = (const float*)d_in[4];

    int B = in_sizes[0] / N_COLS;
    if (B > MAX_B) B = MAX_B;

    float* out = (float*)d_out;
    size_t yElems = (size_t)B * HIDDEN;
    size_t zElems = (size_t)B * TOTAL;
    float* yOut;
    float* zOut;
    if ((long long)out_size == (long long)(yElems + zElems)) {
        yOut = out; zOut = out + yElems;
    } else {
        yOut = nullptr; zOut = out;
    }

    cudaFuncSetAttribute(decode_gemm_mma, cudaFuncAttributeMaxDynamicSharedMemorySize, SMEM_NEED);

    prep_kernel<<<16000, 256>>>(W_enc, (const float4*)W_dec);
    encode_kernel<<<B, HIDDEN>>>(x_cat, b_enc, yOut);

    int mBlocks = B / GM;                       // 16
    int ySplit = (mBlocks % 2 == 0) ? 2 : 1;    // 1000 CTAs
    decode_gemm_mma<<<dim3(TOTAL / GN, ySplit), NTHREADS, SMEM_NEED>>>(b_dec, zOut, mBlocks);
}

// round 7
// speedup vs baseline: 1.5645x; 1.5645x over previous
#include <cuda_runtime.h>
#include <cuda_fp16.h>
#include <cstdint>

#define N_COLS   32
#define CAT_DIM  2000
#define TOTAL    64000
#define HIDDEN   128
#define MAX_B    2048

// -------- device scratch (no allocations allowed) --------
__device__ float  g_WT[(size_t)TOTAL * HIDDEN];   // W_enc^T for coalesced gathers
__device__ __half g_Wd[(size_t)TOTAL * HIDDEN];   // W_dec fp16
__device__ __half g_yh[(size_t)MAX_B * HIDDEN];   // sigmoid(y) fp16

// ---------------------------------------------------------------------------
// 1) Fused prep: blocks [0,8000) transpose W_enc -> g_WT;
//    blocks [8000,16000) convert W_dec fp32 -> fp16.
// ---------------------------------------------------------------------------
__global__ void prep_kernel(const float* __restrict__ W,
                            const float4* __restrict__ Wd) {
    if (blockIdx.x < 8000) {
        __shared__ float tile[32][33];
        int bx = blockIdx.x % 2000, by = blockIdx.x / 2000;
        int tx = threadIdx.x & 31, ty = threadIdx.x >> 5;   // 32 x 8
        int v = bx * 32 + tx;
        int h = by * 32 + ty;
        #pragma unroll
        for (int j = 0; j < 32; j += 8)
            tile[ty + j][tx] = W[(size_t)(h + j) * TOTAL + v];
        __syncthreads();
        int h2 = by * 32 + tx;
        int v2 = bx * 32 + ty;
        #pragma unroll
        for (int j = 0; j < 32; j += 8)
            g_WT[(size_t)(v2 + j) * HIDDEN + h2] = tile[tx][ty + j];
    } else {
        size_t i = (size_t)(blockIdx.x - 8000) * blockDim.x + threadIdx.x;
        float4 w = Wd[i];
        __half2* o2 = (__half2*)g_Wd;
        o2[i * 2 + 0] = __floats2half2_rn(w.x, w.y);
        o2[i * 2 + 1] = __floats2half2_rn(w.z, w.w);
    }
}

// ---------------------------------------------------------------------------
// 2) Encode: gather-sum + sigmoid; emit y (fp32 out) and fp16 copy.
// ---------------------------------------------------------------------------
__global__ void encode_kernel(const int* __restrict__ x_cat,
                              const float* __restrict__ b_enc,
                              float* __restrict__ y_out) {
    int b = blockIdx.x;
    int h = threadIdx.x;
    __shared__ int gidx[N_COLS];
    if (h < N_COLS) gidx[h] = x_cat[b * N_COLS + h] + h * CAT_DIM;
    __syncthreads();
    float acc = b_enc[h];
    #pragma unroll
    for (int i = 0; i < N_COLS; i++)
        acc += g_WT[(size_t)gidx[i] * HIDDEN + h];
    float s = 1.0f / (1.0f + expf(-acc));
    if (y_out) y_out[(size_t)b * HIDDEN + h] = s;
    g_yh[(size_t)b * HIDDEN + h] = __float2half_rn(s);
}

// ---------------------------------------------------------------------------
// 3) Decode GEMM via mma.sync m16n8k16 fp16, single pass.
//    CTA tile 128m x 128n, K=128 resident; 512 threads = 16 warps (4M x 4N),
//    warp tile 32x32. A double-buffered with cp.async across M-tiles.
// ---------------------------------------------------------------------------
#define GM 128
#define GN 128
#define NTHREADS 512

#define OFF_BIAS   0
#define OFF_B      1024
#define OFF_A0     (OFF_B  + 32768)
#define OFF_A1     (OFF_A0 + 32768)
#define SMEM_END   (OFF_A1 + 32768)
#define SMEM_NEED  (SMEM_END + 1024)

__device__ __forceinline__ uint32_t smem_u32(const void* p) {
    return (uint32_t)__cvta_generic_to_shared(p);
}
// Blocked-atom SW128 byte offset within a [128 rows x 128 k fp16] tile.
__device__ __forceinline__ uint32_t tile_off(int r, int i /*16B chunk 0..15*/) {
    uint32_t off = (uint32_t)(((r >> 3) + ((i >> 3) << 4)) << 10)
                 + (uint32_t)((r & 7) << 7) + (uint32_t)((i & 7) << 4);
    return off ^ ((off >> 3) & 0x70);
}
__device__ __forceinline__ void cp16(uint32_t dst, const void* src) {
    asm volatile("cp.async.cg.shared.global [%0], [%1], 16;"
                 :: "r"(dst), "l"(src) : "memory");
}
__device__ __forceinline__ void ldsm_x4(uint32_t* f, uint32_t addr) {
    asm volatile("ldmatrix.sync.aligned.m8n8.x4.shared.b16 {%0,%1,%2,%3}, [%4];"
                 : "=r"(f[0]), "=r"(f[1]), "=r"(f[2]), "=r"(f[3]) : "r"(addr));
}
__device__ __forceinline__ void mma_f16(float* c, const uint32_t* a, const uint32_t* b) {
    asm volatile(
        "mma.sync.aligned.m16n8k16.row.col.f32.f16.f16.f32 "
        "{%0,%1,%2,%3}, {%4,%5,%6,%7}, {%8,%9}, {%0,%1,%2,%3};"
        : "+f"(c[0]), "+f"(c[1]), "+f"(c[2]), "+f"(c[3])
        : "r"(a[0]), "r"(a[1]), "r"(a[2]), "r"(a[3]), "r"(b[0]), "r"(b[1]));
}
__device__ __forceinline__ void stcs2(float* p, float2 v) {
    asm volatile("st.global.cs.v2.f32 [%0], {%1,%2};" :: "l"(p), "f"(v.x), "f"(v.y) : "memory");
}

__global__ __launch_bounds__(NTHREADS, 1)
void decode_gemm_mma(const float* __restrict__ bias, float* __restrict__ C,
                     int mBlocks) {
    extern __shared__ char smem_raw[];
    uint32_t raw = smem_u32(smem_raw);
    uint32_t base = (raw + 1023u) & ~1023u;
    char* sm = smem_raw + (base - raw);

    const int tid = threadIdx.x;
    const int wid = tid >> 5, lane = tid & 31;
    const int warpM = wid >> 2;          // 0..3
    const int warpN = wid & 3;           // 0..3
    const int v0 = blockIdx.x * GN;
    const int mPer = mBlocks / gridDim.y;
    const int mBeg = blockIdx.y * mPer;

    // bias stage
    if (tid < GN) *(float*)(sm + OFF_BIAS + tid * 4) = bias[v0 + tid];

    // B tile, swizzled (once per CTA). 2048 uint4.
    #pragma unroll
    for (int it = 0; it < 4; it++) {
        int idx = it * NTHREADS + tid;
        int r = idx >> 4, i = idx & 15;
        uint32_t so = tile_off(r, i);
        *(uint4*)(sm + OFF_B + so) = ((const uint4*)(g_Wd + (size_t)(v0 + r) * HIDDEN))[i];
    }

    // prefetch A tile 0 into buffer 0 (cp.async): 2048 uint4
    {
        const int m0 = mBeg * GM;
        #pragma unroll
        for (int it = 0; it < 4; it++) {
            int idx = it * NTHREADS + tid;
            int r = idx >> 4, i = idx & 15;
            cp16(base + OFF_A0 + tile_off(r, i),
                 (const char*)(g_yh + (size_t)(m0 + r) * HIDDEN) + i * 16);
        }
        asm volatile("cp.async.commit_group;" ::: "memory");
    }

    // per-thread ldmatrix base addresses
    const int aRow = warpM * 32 + (lane & 15);                      // + mt*16
    const int aChk = (lane >> 4);                                   // + ks*2
    const int bRow = warpN * 32 + ((lane >> 4) << 3) + (lane & 7);  // + bt*16
    const int bChk = (lane >> 3) & 1;                               // + ks*2

    const uint32_t AOFF[2] = {base + OFF_A0, base + OFF_A1};

    for (int mi = 0; mi < mPer; mi++) {
        const int m0 = (mBeg + mi) * GM;
        const int buf = mi & 1;

        asm volatile("cp.async.wait_group 0;" ::: "memory");
        __syncthreads();

        // prefetch next A tile into the other buffer
        if (mi + 1 < mPer) {
            const int m1 = (mBeg + mi + 1) * GM;
            const uint32_t dst = AOFF[buf ^ 1];
            #pragma unroll
            for (int it = 0; it < 4; it++) {
                int idx = it * NTHREADS + tid;
                int r = idx >> 4, i = idx & 15;
                cp16(dst + tile_off(r, i),
                     (const char*)(g_yh + (size_t)(m1 + r) * HIDDEN) + i * 16);
            }
            asm volatile("cp.async.commit_group;" ::: "memory");
        }

        float acc[2][4][4];
        #pragma unroll
        for (int mt = 0; mt < 2; mt++)
            #pragma unroll
            for (int nt = 0; nt < 4; nt++)
                #pragma unroll
                for (int q = 0; q < 4; q++)
                    acc[mt][nt][q] = 0.0f;

        const uint32_t aBase = AOFF[buf];

        #pragma unroll
        for (int ks = 0; ks < 8; ks++) {
            uint32_t ah[2][4];
            #pragma unroll
            for (int mt = 0; mt < 2; mt++)
                ldsm_x4(ah[mt], aBase + tile_off(aRow + mt * 16, ks * 2 + aChk));
            uint32_t bh[4][2];
            #pragma unroll
            for (int bt = 0; bt < 2; bt++) {
                uint32_t fh[4];
                ldsm_x4(fh, base + OFF_B + tile_off(bRow + bt * 16, ks * 2 + bChk));
                bh[bt * 2 + 0][0] = fh[0]; bh[bt * 2 + 0][1] = fh[1];
                bh[bt * 2 + 1][0] = fh[2]; bh[bt * 2 + 1][1] = fh[3];
            }
            #pragma unroll
            for (int mt = 0; mt < 2; mt++)
                #pragma unroll
                for (int nt = 0; nt < 4; nt++)
                    mma_f16(acc[mt][nt], ah[mt], bh[nt]);
        }

        // epilogue: bias + streaming float2 stores
        const int cCol = warpN * 32 + 2 * (lane & 3);
        const int cRow = warpM * 32 + (lane >> 2);
        #pragma unroll
        for (int mt = 0; mt < 2; mt++) {
            #pragma unroll
            for (int nt = 0; nt < 4; nt++) {
                int col = cCol + nt * 8;
                float bx = *(float*)(sm + OFF_BIAS + col * 4);
                float by = *(float*)(sm + OFF_BIAS + (col + 1) * 4);
                size_t r0 = (size_t)(m0 + cRow + mt * 16) * TOTAL + v0 + col;
                size_t r1 = r0 + 8 * TOTAL;
                stcs2(&C[r0], make_float2(acc[mt][nt][0] + bx, acc[mt][nt][1] + by));
                stcs2(&C[r1], make_float2(acc[mt][nt][2] + bx, acc[mt][nt][3] + by));
            }
        }
        __syncthreads();   // protect smem A buffer reuse ordering
    }
}

// ---------------------------------------------------------------------------
// Launch
// ---------------------------------------------------------------------------
extern "C" void kernel_launch(void* const* d_in, const int* in_sizes, int n_in,
                              void* d_out, int out_size) {
    const int*   x_cat = (const int*)d_in[0];
    const float* W_enc = (const float*)d_in[1];
    const float* b_enc = (const float*)d_in[2];
    const float* W_dec = (const float*)d_in[3];
    const float* b_dec = (const float*)d_in[4];

    int B = in_sizes[0] / N_COLS;
    if (B > MAX_B) B = MAX_B;

    float* out = (float*)d_out;
    size_t yElems = (size_t)B * HIDDEN;
    size_t zElems = (size_t)B * TOTAL;
    float* yOut;
    float* zOut;
    if ((long long)out_size == (long long)(yElems + zElems)) {
        yOut = out; zOut = out + yElems;
    } else {
        yOut = nullptr; zOut = out;
    }

    cudaFuncSetAttribute(decode_gemm_mma, cudaFuncAttributeMaxDynamicSharedMemorySize, SMEM_NEED);

    prep_kernel<<<16000, 256>>>(W_enc, (const float4*)W_dec);
    encode_kernel<<<B, HIDDEN>>>(x_cat, b_enc, yOut);

    int mBlocks = B / GM;                       // 16
    int ySplit = (mBlocks % 2 == 0) ? 2 : 1;    // 1000 CTAs
    decode_gemm_mma<<<dim3(TOTAL / GN, ySplit), NTHREADS, SMEM_NEED>>>(b_dec, zOut, mBlocks);
}

// round 8
// speedup vs baseline: 1.8763x; 1.1993x over previous
#include <cuda_runtime.h>
#include <cuda_fp16.h>
#include <cstdint>

#define N_COLS   32
#define CAT_DIM  2000
#define TOTAL    64000
#define HIDDEN   128
#define MAX_B    2048

// -------- device scratch (no allocations allowed) --------
__device__ float  g_WT[(size_t)TOTAL * HIDDEN];   // W_enc^T for coalesced gathers
__device__ __half g_Wd[(size_t)TOTAL * HIDDEN];   // W_dec fp16
__device__ __half g_yh[(size_t)MAX_B * HIDDEN];   // sigmoid(y) fp16

// ---------------------------------------------------------------------------
// 1) Fused prep: blocks [0,8000) transpose W_enc -> g_WT;
//    blocks [8000,16000) convert W_dec fp32 -> fp16.
// ---------------------------------------------------------------------------
__global__ void prep_kernel(const float* __restrict__ W,
                            const float4* __restrict__ Wd) {
    if (blockIdx.x < 8000) {
        __shared__ float tile[32][33];
        int bx = blockIdx.x % 2000, by = blockIdx.x / 2000;
        int tx = threadIdx.x & 31, ty = threadIdx.x >> 5;   // 32 x 8
        int v = bx * 32 + tx;
        int h = by * 32 + ty;
        #pragma unroll
        for (int j = 0; j < 32; j += 8)
            tile[ty + j][tx] = W[(size_t)(h + j) * TOTAL + v];
        __syncthreads();
        int h2 = by * 32 + tx;
        int v2 = bx * 32 + ty;
        #pragma unroll
        for (int j = 0; j < 32; j += 8)
            g_WT[(size_t)(v2 + j) * HIDDEN + h2] = tile[tx][ty + j];
    } else {
        size_t i = (size_t)(blockIdx.x - 8000) * blockDim.x + threadIdx.x;
        float4 w = Wd[i];
        __half2* o2 = (__half2*)g_Wd;
        o2[i * 2 + 0] = __floats2half2_rn(w.x, w.y);
        o2[i * 2 + 1] = __floats2half2_rn(w.z, w.w);
    }
}

// ---------------------------------------------------------------------------
// 2) Encode: gather-sum + sigmoid; emit y (fp32 out) and fp16 copy.
// ---------------------------------------------------------------------------
__global__ void encode_kernel(const int* __restrict__ x_cat,
                              const float* __restrict__ b_enc,
                              float* __restrict__ y_out) {
    int b = blockIdx.x;
    int h = threadIdx.x;
    __shared__ int gidx[N_COLS];
    if (h < N_COLS) gidx[h] = x_cat[b * N_COLS + h] + h * CAT_DIM;
    __syncthreads();
    float acc = b_enc[h];
    #pragma unroll
    for (int i = 0; i < N_COLS; i++)
        acc += g_WT[(size_t)gidx[i] * HIDDEN + h];
    float s = 1.0f / (1.0f + expf(-acc));
    if (y_out) y_out[(size_t)b * HIDDEN + h] = s;
    g_yh[(size_t)b * HIDDEN + h] = __float2half_rn(s);
}

// ---------------------------------------------------------------------------
// 3) Decode GEMM via mma.sync m16n8k16 fp16, single pass.
//    CTA tile 128m x 128n, K=128 resident; 512 threads = 16 warps (4M x 4N),
//    warp tile 32x32. B FRAGMENTS HOISTED to registers for the whole CTA
//    (B is invariant across the CTA's M-tiles); A double-buffered cp.async.
// ---------------------------------------------------------------------------
#define GM 128
#define GN 128
#define NTHREADS 512

#define OFF_BIAS   0
#define OFF_B      1024
#define OFF_A0     (OFF_B  + 32768)
#define OFF_A1     (OFF_A0 + 32768)
#define SMEM_END   (OFF_A1 + 32768)
#define SMEM_NEED  (SMEM_END + 1024)

__device__ __forceinline__ uint32_t smem_u32(const void* p) {
    return (uint32_t)__cvta_generic_to_shared(p);
}
// Blocked-atom SW128 byte offset within a [128 rows x 128 k fp16] tile.
__device__ __forceinline__ uint32_t tile_off(int r, int i /*16B chunk 0..15*/) {
    uint32_t off = (uint32_t)(((r >> 3) + ((i >> 3) << 4)) << 10)
                 + (uint32_t)((r & 7) << 7) + (uint32_t)((i & 7) << 4);
    return off ^ ((off >> 3) & 0x70);
}
__device__ __forceinline__ void cp16(uint32_t dst, const void* src) {
    asm volatile("cp.async.cg.shared.global [%0], [%1], 16;"
                 :: "r"(dst), "l"(src) : "memory");
}
__device__ __forceinline__ void ldsm_x4(uint32_t* f, uint32_t addr) {
    asm volatile("ldmatrix.sync.aligned.m8n8.x4.shared.b16 {%0,%1,%2,%3}, [%4];"
                 : "=r"(f[0]), "=r"(f[1]), "=r"(f[2]), "=r"(f[3]) : "r"(addr));
}
__device__ __forceinline__ void mma_f16(float* c, const uint32_t* a, const uint32_t* b) {
    asm volatile(
        "mma.sync.aligned.m16n8k16.row.col.f32.f16.f16.f32 "
        "{%0,%1,%2,%3}, {%4,%5,%6,%7}, {%8,%9}, {%0,%1,%2,%3};"
        : "+f"(c[0]), "+f"(c[1]), "+f"(c[2]), "+f"(c[3])
        : "r"(a[0]), "r"(a[1]), "r"(a[2]), "r"(a[3]), "r"(b[0]), "r"(b[1]));
}
__device__ __forceinline__ void stcs2(float* p, float2 v) {
    asm volatile("st.global.cs.v2.f32 [%0], {%1,%2};" :: "l"(p), "f"(v.x), "f"(v.y) : "memory");
}

__global__ __launch_bounds__(NTHREADS, 1)
void decode_gemm_mma(const float* __restrict__ bias, float* __restrict__ C,
                     int mBlocks) {
    extern __shared__ char smem_raw[];
    uint32_t raw = smem_u32(smem_raw);
    uint32_t base = (raw + 1023u) & ~1023u;
    char* sm = smem_raw + (base - raw);

    const int tid = threadIdx.x;
    const int wid = tid >> 5, lane = tid & 31;
    const int warpM = wid >> 2;          // 0..3
    const int warpN = wid & 3;           // 0..3
    const int v0 = blockIdx.x * GN;
    const int mPer = mBlocks / gridDim.y;
    const int mBeg = blockIdx.y * mPer;

    // bias stage
    if (tid < GN) *(float*)(sm + OFF_BIAS + tid * 4) = bias[v0 + tid];

    // B tile, swizzled (once per CTA). 2048 uint4.
    #pragma unroll
    for (int it = 0; it < 4; it++) {
        int idx = it * NTHREADS + tid;
        int r = idx >> 4, i = idx & 15;
        uint32_t so = tile_off(r, i);
        *(uint4*)(sm + OFF_B + so) = ((const uint4*)(g_Wd + (size_t)(v0 + r) * HIDDEN))[i];
    }

    // prefetch A tile 0 into buffer 0 (cp.async)
    {
        const int m0 = mBeg * GM;
        #pragma unroll
        for (int it = 0; it < 4; it++) {
            int idx = it * NTHREADS + tid;
            int r = idx >> 4, i = idx & 15;
            cp16(base + OFF_A0 + tile_off(r, i),
                 (const char*)(g_yh + (size_t)(m0 + r) * HIDDEN) + i * 16);
        }
        asm volatile("cp.async.commit_group;" ::: "memory");
    }

    // per-thread ldmatrix base addresses
    const int aRow = warpM * 32 + (lane & 15);                      // + mt*16
    const int aChk = (lane >> 4);                                   // + ks*2
    const int bRow = warpN * 32 + ((lane >> 4) << 3) + (lane & 7);  // + bt*16
    const int bChk = (lane >> 3) & 1;                               // + ks*2

    __syncthreads();   // B smem ready for fragment preload

    // ---- hoist ALL B fragments to registers (invariant across M-tiles) ----
    uint32_t bh[8][4][2];
    #pragma unroll
    for (int ks = 0; ks < 8; ks++) {
        #pragma unroll
        for (int bt = 0; bt < 2; bt++) {
            uint32_t fh[4];
            ldsm_x4(fh, base + OFF_B + tile_off(bRow + bt * 16, ks * 2 + bChk));
            bh[ks][bt * 2 + 0][0] = fh[0]; bh[ks][bt * 2 + 0][1] = fh[1];
            bh[ks][bt * 2 + 1][0] = fh[2]; bh[ks][bt * 2 + 1][1] = fh[3];
        }
    }

    const uint32_t AOFF[2] = {base + OFF_A0, base + OFF_A1};

    for (int mi = 0; mi < mPer; mi++) {
        const int m0 = (mBeg + mi) * GM;
        const int buf = mi & 1;

        asm volatile("cp.async.wait_group 0;" ::: "memory");
        __syncthreads();   // A(buf) ready; also fences prior readers of buf^1

        // prefetch next A tile into the other buffer
        if (mi + 1 < mPer) {
            const int m1 = (mBeg + mi + 1) * GM;
            const uint32_t dst = AOFF[buf ^ 1];
            #pragma unroll
            for (int it = 0; it < 4; it++) {
                int idx = it * NTHREADS + tid;
                int r = idx >> 4, i = idx & 15;
                cp16(dst + tile_off(r, i),
                     (const char*)(g_yh + (size_t)(m1 + r) * HIDDEN) + i * 16);
            }
            asm volatile("cp.async.commit_group;" ::: "memory");
        }

        float acc[2][4][4];
        #pragma unroll
        for (int mt = 0; mt < 2; mt++)
            #pragma unroll
            for (int nt = 0; nt < 4; nt++)
                #pragma unroll
                for (int q = 0; q < 4; q++)
                    acc[mt][nt][q] = 0.0f;

        const uint32_t aBase = AOFF[buf];

        #pragma unroll
        for (int ks = 0; ks < 8; ks++) {
            uint32_t ah[2][4];
            #pragma unroll
            for (int mt = 0; mt < 2; mt++)
                ldsm_x4(ah[mt], aBase + tile_off(aRow + mt * 16, ks * 2 + aChk));
            #pragma unroll
            for (int mt = 0; mt < 2; mt++)
                #pragma unroll
                for (int nt = 0; nt < 4; nt++)
                    mma_f16(acc[mt][nt], ah[mt], bh[ks][nt]);
        }

        // epilogue: bias + streaming float2 stores (no tail sync needed:
        // next head sync orders all warps' buf reads before overwrite)
        const int cCol = warpN * 32 + 2 * (lane & 3);
        const int cRow = warpM * 32 + (lane >> 2);
        #pragma unroll
        for (int mt = 0; mt < 2; mt++) {
            #pragma unroll
            for (int nt = 0; nt < 4; nt++) {
                int col = cCol + nt * 8;
                float bx = *(float*)(sm + OFF_BIAS + col * 4);
                float by = *(float*)(sm + OFF_BIAS + (col + 1) * 4);
                size_t r0 = (size_t)(m0 + cRow + mt * 16) * TOTAL + v0 + col;
                size_t r1 = r0 + 8 * TOTAL;
                stcs2(&C[r0], make_float2(acc[mt][nt][0] + bx, acc[mt][nt][1] + by));
                stcs2(&C[r1], make_float2(acc[mt][nt][2] + bx, acc[mt][nt][3] + by));
            }
        }
    }
}

// ---------------------------------------------------------------------------
// Launch
// ---------------------------------------------------------------------------
extern "C" void kernel_launch(void* const* d_in, const int* in_sizes, int n_in,
                              void* d_out, int out_size) {
    const int*   x_cat = (const int*)d_in[0];
    const float* W_enc = (const float*)d_in[1];
    const float* b_enc = (const float*)d_in[2];
    const float* W_dec = (const float*)d_in[3];
    const float* b_dec = (const float*)d_in[4];

    int B = in_sizes[0] / N_COLS;
    if (B > MAX_B) B = MAX_B;

    float* out = (float*)d_out;
    size_t yElems = (size_t)B * HIDDEN;
    size_t zElems = (size_t)B * TOTAL;
    float* yOut;
    float* zOut;
    if ((long long)out_size == (long long)(yElems + zElems)) {
        yOut = out; zOut = out + yElems;
    } else {
        yOut = nullptr; zOut = out;
    }

    cudaFuncSetAttribute(decode_gemm_mma, cudaFuncAttributeMaxDynamicSharedMemorySize, SMEM_NEED);

    prep_kernel<<<16000, 256>>>(W_enc, (const float4*)W_dec);
    encode_kernel<<<B, HIDDEN>>>(x_cat, b_enc, yOut);

    int mBlocks = B / GM;                       // 16
    int ySplit = (mBlocks % 2 == 0) ? 2 : 1;    // 1000 CTAs
    decode_gemm_mma<<<dim3(TOTAL / GN, ySplit), NTHREADS, SMEM_NEED>>>(b_dec, zOut, mBlocks);
}